// round 1
// baseline (speedup 1.0000x reference)
#include <cuda_runtime.h>
#include <math.h>

#define BATCH 16384
#define HID   256
#define LATD  64
#define NSTEP 63

#define OUT_S_OFF  (BATCH*LATD)
#define OUT_Z_OFF  (2*BATCH*LATD)
#define ZSLICE     (BATCH*LATD)

// ---------------- scratch (static device arrays; no allocation) ----------------
__device__ float g_h  [BATCH*HID];
__device__ float g_b1 [BATCH*HID];
__device__ float g_b2 [BATCH*HID];
__device__ float g_lat[BATCH*2*LATD];
__device__ float g_dr [BATCH*LATD];
__device__ float g_df [BATCH*LATD];

enum { OP_NONE=0, OP_SWISH=1, OP_SOFTPLUS=2, OP_RESADD=3 };

__device__ __forceinline__ float f_swish(float v){
    return v * (1.0f / (1.0f + __expf(-v)));
}
__device__ __forceinline__ float f_softplus(float v){
    // stable: max(x,0) + log1p(exp(-|x|))
    return fmaxf(v, 0.0f) + log1pf(__expf(-fabsf(v)));
}

// ---------------------------------------------------------------------------
// Tiled fp32 GEMM: C[M,N] = op(A[M,K] @ B[K,N] + bias) (+ residual)
// BM=128, BN=64, BK=32, 256 threads, 8x4 register micro-tile per thread.
// TZ mode: A is logically [t, Z] with K=65, Z stored [M,64]; col 0 = ts[tstep].
// ---------------------------------------------------------------------------
template<int OP, bool TZ>
__global__ void __launch_bounds__(256, 3) gemm_k(
    const float* __restrict__ A, const float* __restrict__ B,
    const float* __restrict__ bias, const float* __restrict__ res,
    float* __restrict__ C, int N, int K,
    const float* __restrict__ ts, int tstep)
{
    __shared__ float As[32][128];
    __shared__ float Bs[32][64];

    const int tid = threadIdx.x;
    const int m0 = blockIdx.x * 128;
    const int n0 = blockIdx.y * 64;

    float tval = 0.0f;
    if (TZ) tval = __ldg(&ts[tstep]);

    const int tm = tid >> 4;          // 0..15 -> rows tm*8 .. +7
    const int tn = tid & 15;          // 0..15 -> cols tn*4 .. +3

    const int a_m = tid >> 1;         // 0..127
    const int a_k = (tid & 1) << 4;   // 0 or 16
    const int b_k = tid >> 3;         // 0..31
    const int b_n = (tid & 7) << 3;   // 0..56 step 8

    float acc[8][4];
    #pragma unroll
    for (int i = 0; i < 8; i++)
        #pragma unroll
        for (int j = 0; j < 4; j++) acc[i][j] = 0.0f;

    for (int k0 = 0; k0 < K; k0 += 32) {
        // ---- load A tile (transposed into As[k][m]) ----
        if (TZ) {
            #pragma unroll
            for (int i = 0; i < 16; i++) {
                int kk = k0 + a_k + i;
                float v = 0.0f;
                if (kk == 0) v = tval;
                else if (kk < K) v = A[(size_t)(m0 + a_m) * LATD + (kk - 1)];
                As[a_k + i][a_m] = v;
            }
        } else {
            // all non-TZ GEMMs have K % 32 == 0 (K = 256)
            const float* Ap = A + (size_t)(m0 + a_m) * K + k0 + a_k;
            #pragma unroll
            for (int i = 0; i < 16; i += 4) {
                float4 v = *reinterpret_cast<const float4*>(Ap + i);
                As[a_k + i + 0][a_m] = v.x;
                As[a_k + i + 1][a_m] = v.y;
                As[a_k + i + 2][a_m] = v.z;
                As[a_k + i + 3][a_m] = v.w;
            }
        }
        // ---- load B tile ----
        {
            int kk = k0 + b_k;
            float4 v0 = make_float4(0.f,0.f,0.f,0.f), v1 = v0;
            if (kk < K) {
                const float* Bp = B + (size_t)kk * N + n0 + b_n;
                v0 = *reinterpret_cast<const float4*>(Bp);
                v1 = *reinterpret_cast<const float4*>(Bp + 4);
            }
            *reinterpret_cast<float4*>(&Bs[b_k][b_n])     = v0;
            *reinterpret_cast<float4*>(&Bs[b_k][b_n + 4]) = v1;
        }
        __syncthreads();

        #pragma unroll
        for (int k = 0; k < 32; k++) {
            float4 a0 = *reinterpret_cast<const float4*>(&As[k][tm*8]);
            float4 a1 = *reinterpret_cast<const float4*>(&As[k][tm*8+4]);
            float4 b  = *reinterpret_cast<const float4*>(&Bs[k][tn*4]);
            float av[8] = {a0.x,a0.y,a0.z,a0.w,a1.x,a1.y,a1.z,a1.w};
            float bv[4] = {b.x,b.y,b.z,b.w};
            #pragma unroll
            for (int i = 0; i < 8; i++)
                #pragma unroll
                for (int j = 0; j < 4; j++)
                    acc[i][j] = fmaf(av[i], bv[j], acc[i][j]);
        }
        __syncthreads();
    }

    // ---- epilogue ----
    const int n = n0 + tn*4;
    float4 bb = *reinterpret_cast<const float4*>(&bias[n]);
    float bv4[4] = {bb.x, bb.y, bb.z, bb.w};
    #pragma unroll
    for (int i = 0; i < 8; i++) {
        int m = m0 + tm*8 + i;
        float o[4];
        #pragma unroll
        for (int j = 0; j < 4; j++) {
            float v = acc[i][j] + bv4[j];
            if constexpr (OP == OP_SWISH)    v = f_swish(v);
            if constexpr (OP == OP_SOFTPLUS) v = f_softplus(v);
            if constexpr (OP == OP_RESADD)   v += res[(size_t)m * N + n + j];
            o[j] = v;
        }
        *reinterpret_cast<float4*>(C + (size_t)m * N + n) =
            make_float4(o[0], o[1], o[2], o[3]);
    }
}

// ---------------- elementwise: split latent into mu and s = exp(0.5*logvar) ----
__global__ void latent_out_k(const float* __restrict__ lat, float* __restrict__ out)
{
    int idx = blockIdx.x * 256 + threadIdx.x;      // BATCH*LATD threads
    int row = idx >> 6;
    int j   = idx & 63;
    out[idx]             = lat[row * (2*LATD) + j];
    out[OUT_S_OFF + idx] = __expf(0.5f * lat[row * (2*LATD) + LATD + j]);
}

// ---------------- elementwise: Euler–Maruyama step ----------------
__global__ void sde_update_k(const float* __restrict__ ts, const float* __restrict__ noise,
                             float* __restrict__ out, int k)
{
    int idx = blockIdx.x * 256 + threadIdx.x;      // BATCH*LATD threads
    float t0 = __ldg(&ts[k]);
    float t1 = __ldg(&ts[k+1]);
    float dt = t1 - t0;
    float sq = sqrtf(dt);
    const float* zp = out + OUT_Z_OFF + (size_t)k * ZSLICE;
    float zn = zp[idx] + g_dr[idx] * dt
             + g_df[idx] * sq * noise[(size_t)k * ZSLICE + idx];
    out[OUT_Z_OFF + (size_t)(k+1) * ZSLICE + idx] = zn;
}

// ---------------------------------------------------------------------------
extern "C" void kernel_launch(void* const* d_in, const int* in_sizes, int n_in,
                              void* d_out, int out_size)
{
    const float* x     = (const float*)d_in[0];
    const float* ts    = (const float*)d_in[1];
    const float* noise = (const float*)d_in[2];
    const float* W_in  = (const float*)d_in[3];
    const float* b_in  = (const float*)d_in[4];
    const float* Wb1   = (const float*)d_in[5];
    const float* bb1   = (const float*)d_in[6];
    const float* Wb2   = (const float*)d_in[7];
    const float* bb2   = (const float*)d_in[8];
    const float* W_fo  = (const float*)d_in[9];
    const float* b_fo  = (const float*)d_in[10];
    const float* W_lat = (const float*)d_in[11];
    const float* b_lat = (const float*)d_in[12];
    const float* W_init= (const float*)d_in[13];
    const float* b_init= (const float*)d_in[14];
    const float* Wd1   = (const float*)d_in[15];
    const float* bd1   = (const float*)d_in[16];
    const float* Wd2   = (const float*)d_in[17];
    const float* bd2   = (const float*)d_in[18];
    const float* Wd3   = (const float*)d_in[19];
    const float* bd3   = (const float*)d_in[20];
    const float* Wg1   = (const float*)d_in[21];
    const float* bg1   = (const float*)d_in[22];
    const float* Wg2   = (const float*)d_in[23];
    const float* bg2   = (const float*)d_in[24];
    float* out = (float*)d_out;

    float *h, *b1, *b2, *lat, *dr, *df;
    cudaGetSymbolAddress((void**)&h,   g_h);
    cudaGetSymbolAddress((void**)&b1,  g_b1);
    cudaGetSymbolAddress((void**)&b2,  g_b2);
    cudaGetSymbolAddress((void**)&lat, g_lat);
    cudaGetSymbolAddress((void**)&dr,  g_dr);
    cudaGetSymbolAddress((void**)&df,  g_df);

    dim3 blk(256);
    dim3 g256(BATCH/128, 4);
    dim3 g128(BATCH/128, 2);
    dim3 g64 (BATCH/128, 1);

    // ---- encoder ----
    gemm_k<OP_SWISH,false><<<g256, blk>>>(x, W_in, b_in, nullptr, h, 256, 256, nullptr, 0);
    for (int i = 0; i < 3; i++) {
        gemm_k<OP_SWISH, false><<<g256, blk>>>(h,  Wb1 + (size_t)i*HID*HID, bb1 + i*HID,
                                               nullptr, b1, 256, 256, nullptr, 0);
        // in-place residual: each element read (res) and written (C) by the same thread
        gemm_k<OP_RESADD,false><<<g256, blk>>>(b1, Wb2 + (size_t)i*HID*HID, bb2 + i*HID,
                                               h, h, 256, 256, nullptr, 0);
    }
    gemm_k<OP_NONE,false><<<g256, blk>>>(h,  W_fo,  b_fo,  nullptr, b1,  256, 256, nullptr, 0);
    gemm_k<OP_NONE,false><<<g128, blk>>>(b1, W_lat, b_lat, nullptr, lat, 128, 256, nullptr, 0);
    latent_out_k<<<BATCH*LATD/256, blk>>>(lat, out);
    // z0 straight into z_path[0]
    gemm_k<OP_NONE,false><<<g64,  blk>>>(b1, W_init, b_init, nullptr, out + OUT_Z_OFF, 64, 256, nullptr, 0);

    // ---- SDE scan: z lives in the z_path slices of out ----
    for (int k = 0; k < NSTEP; k++) {
        const float* z = out + OUT_Z_OFF + (size_t)k * ZSLICE;
        gemm_k<OP_SWISH,   true ><<<g256, blk>>>(z,  Wd1, bd1, nullptr, b1, 256,  65, ts, k);
        gemm_k<OP_SWISH,   false><<<g256, blk>>>(b1, Wd2, bd2, nullptr, b2, 256, 256, nullptr, 0);
        gemm_k<OP_NONE,    false><<<g64,  blk>>>(b2, Wd3, bd3, nullptr, dr,  64, 256, nullptr, 0);
        gemm_k<OP_SWISH,   true ><<<g256, blk>>>(z,  Wg1, bg1, nullptr, b1, 256,  65, ts, k);
        gemm_k<OP_SOFTPLUS,false><<<g64,  blk>>>(b1, Wg2, bg2, nullptr, df,  64, 256, nullptr, 0);
        sde_update_k<<<BATCH*LATD/256, blk>>>(ts, noise, out, k);
    }
}

// round 3
// speedup vs baseline: 2.0458x; 2.0458x over previous
#include <cuda_runtime.h>
#include <cuda_bf16.h>
#include <stdint.h>
#include <math.h>

#define BATCH 16384
#define HID   256
#define LATD  64
#define NSTEP 63

#define OUT_S_OFF  (BATCH*LATD)
#define OUT_Z_OFF  (2*BATCH*LATD)
#define ZSLICE     (BATCH*LATD)

// ---------------- scratch (static device arrays; no allocation) ----------------
__device__ __nv_bfloat16 g_xh[BATCH*HID], g_xl[BATCH*HID];
__device__ __nv_bfloat16 g_ah[BATCH*HID], g_al[BATCH*HID];
__device__ __nv_bfloat16 g_bh[BATCH*HID], g_bl[BATCH*HID];
__device__ float g_hres[BATCH*HID];
__device__ float g_lat [BATCH*2*LATD];
__device__ float g_dr  [BATCH*LATD];

// weight scratch: elementwise hi/lo split, natural [K][N] layout (no transpose)
#define OFF_WIN   0
#define OFF_WB1   65536
#define OFF_WB2   (OFF_WB1 + 3*65536)
#define OFF_WFO   (OFF_WB2 + 3*65536)
#define OFF_WLAT  (OFF_WFO + 65536)
#define OFF_WINIT (OFF_WLAT + 32768)
#define OFF_WD1   (OFF_WINIT + 16384)
#define OFF_WD2   (OFF_WD1 + 16384)
#define OFF_WD3   (OFF_WD2 + 65536)
#define OFF_WG1   (OFF_WD3 + 16384)
#define OFF_WG2   (OFF_WG1 + 16384)
#define WT_TOTAL  (OFF_WG2 + 16384)

__device__ __nv_bfloat16 g_wh[WT_TOTAL];
__device__ __nv_bfloat16 g_wl[WT_TOTAL];

enum { ACT_NONE=0, ACT_SWISH=1, ACT_SOFTPLUS=2 };

__device__ __forceinline__ float f_swish(float v){
    return v * (1.0f / (1.0f + __expf(-v)));
}
__device__ __forceinline__ float f_softplus(float v){
    return fmaxf(v, 0.0f) + log1pf(__expf(-fabsf(v)));
}

__device__ __forceinline__ uint32_t smem_u32(const void* p){
    uint32_t a;
    asm("{ .reg .u64 t; cvta.to.shared.u64 t, %1; cvt.u32.u64 %0, t; }" : "=r"(a) : "l"(p));
    return a;
}
__device__ __forceinline__ void ldsm4(uint32_t (&r)[4], uint32_t addr){
    asm volatile("ldmatrix.sync.aligned.m8n8.x4.shared.b16 {%0,%1,%2,%3}, [%4];"
        : "=r"(r[0]),"=r"(r[1]),"=r"(r[2]),"=r"(r[3]) : "r"(addr));
}
__device__ __forceinline__ void ldsm4t(uint32_t (&r)[4], uint32_t addr){
    asm volatile("ldmatrix.sync.aligned.m8n8.x4.trans.shared.b16 {%0,%1,%2,%3}, [%4];"
        : "=r"(r[0]),"=r"(r[1]),"=r"(r[2]),"=r"(r[3]) : "r"(addr));
}
__device__ __forceinline__ void mma_bf16(float (&d)[4], const uint32_t (&a)[4],
                                         uint32_t b0, uint32_t b1){
    asm volatile(
        "mma.sync.aligned.m16n8k16.row.col.f32.bf16.bf16.f32 "
        "{%0,%1,%2,%3}, {%4,%5,%6,%7}, {%8,%9}, {%0,%1,%2,%3};"
        : "+f"(d[0]),"+f"(d[1]),"+f"(d[2]),"+f"(d[3])
        : "r"(a[0]),"r"(a[1]),"r"(a[2]),"r"(a[3]), "r"(b0),"r"(b1));
}

// ---------------------------------------------------------------------------
// mma.sync bf16 split GEMM.
// C[M=16384, NG] = act(A[M,K] @ B[K,NG] + bias_eff) (+res) (+SDE update)
// A: bf16 hi/lo pair, or (AZ) built on the fly from f32 z (K=64).
// B: bf16 hi/lo, natural [K][NG] layout. 3 products: AhBh + AhBl + AlBh.
// CTA: 128 x BN tile, BK=64 chunks, smem SW128-swizzled, conflict-free ldmatrix.
// TB: bias_eff[n] = bias[n] + ts[kstep] * W0[n]  (fold of the [t,z] concat).
// UPD: epilogue computes z_new = z + dr*dt + softplus(v)*sqrt(dt)*noise.
// ---------------------------------------------------------------------------
template<int K, int NG, int ACT, bool RES, bool WBF, bool WF32, bool AZ, bool TB, bool UPD>
__global__ void __launch_bounds__(256,2) mgemm(
    const __nv_bfloat16* __restrict__ Ah_g, const __nv_bfloat16* __restrict__ Al_g,
    const float* __restrict__ Zsrc,
    const __nv_bfloat16* __restrict__ Bh_g, const __nv_bfloat16* __restrict__ Bl_g,
    const float* __restrict__ bias, const float* __restrict__ W0,
    const float* __restrict__ ts, int kstep,
    const float* __restrict__ resp,
    float* __restrict__ outF,
    __nv_bfloat162* __restrict__ outBh, __nv_bfloat162* __restrict__ outBl,
    const float* __restrict__ drp, const float* __restrict__ noise)
{
    constexpr int BN  = (NG >= 128) ? 128 : 64;
    constexpr int WN  = BN / 2;          // warp n-extent
    constexpr int NP  = WN / 16;         // n-pair tiles per warp
    constexpr int NCH = K / 64;
    constexpr int BSZ = BN * 128;        // bytes per B buffer ([64][BN] bf16)
    constexpr int AHo = 0, ALo = 16384, BHo = 32768, BLo = 32768 + BSZ;

    extern __shared__ char sm[];
    const int tid = threadIdx.x;
    const int lid = tid & 31, wid = tid >> 5;
    const int wm  = wid & 3;             // m sub-block (x32)
    const int wn  = wid >> 2;            // n sub-block (xWN)
    const int m0  = blockIdx.x * 128;
    const int n0c = blockIdx.y * BN;
    const uint32_t sb = smem_u32(sm);

    float acc[2][NP*2][4];
    #pragma unroll
    for (int i=0;i<2;i++)
        #pragma unroll
        for (int j=0;j<NP*2;j++)
            #pragma unroll
            for (int q=0;q<4;q++) acc[i][j][q] = 0.0f;

    for (int c = 0; c < NCH; c++) {
        const int c64 = c * 64;
        if (c) __syncthreads();

        // ---- A chunk -> smem (hi & lo), swizzled [128 rows][64 halves] ----
        if (!AZ) {
            #pragma unroll
            for (int it = 0; it < 4; it++) {
                int g = tid + it*256;
                int row = g >> 3, gg = g & 7;
                uint32_t off = (uint32_t)(row*128 + gg*16);
                off ^= (off >> 3) & 0x70;
                size_t src = (size_t)(m0+row)*K + c64 + gg*8;
                *(uint4*)(sm + AHo + off) = *(const uint4*)(Ah_g + src);
                *(uint4*)(sm + ALo + off) = *(const uint4*)(Al_g + src);
            }
        } else {  // K==64: build from f32 z, split hi/lo on the fly
            #pragma unroll
            for (int it = 0; it < 4; it++) {
                int g = tid + it*256;
                int row = g >> 3, gg = g & 7;
                uint32_t off = (uint32_t)(row*128 + gg*16);
                off ^= (off >> 3) & 0x70;
                const float* zp = Zsrc + (size_t)(m0+row)*64 + gg*8;
                float4 f0 = *(const float4*)zp;
                float4 f1 = *(const float4*)(zp+4);
                float fv[8] = {f0.x,f0.y,f0.z,f0.w,f1.x,f1.y,f1.z,f1.w};
                alignas(16) __nv_bfloat16 hv[8], lv[8];
                #pragma unroll
                for (int j=0;j<8;j++){
                    __nv_bfloat16 h = __float2bfloat16(fv[j]);
                    hv[j]=h; lv[j]=__float2bfloat16(fv[j]-__bfloat162float(h));
                }
                *(uint4*)(sm + AHo + off) = *(const uint4*)hv;
                *(uint4*)(sm + ALo + off) = *(const uint4*)lv;
            }
        }

        // ---- B chunk -> smem (hi & lo), [64 k-rows][BN halves] as 64-wide subtiles ----
        #pragma unroll
        for (int it = 0; it < BN/32; it++) {
            int g = tid + it*256;
            int row, gg;
            if (BN == 128) { row = g >> 4; gg = g & 15; }
            else           { row = g >> 3; gg = g & 7;  }
            int s = gg >> 3, gin = gg & 7;
            uint32_t off = (uint32_t)(row*128 + gin*16);
            off ^= (off >> 3) & 0x70;
            off += (uint32_t)s * 8192;
            size_t src = (size_t)(c64+row)*NG + n0c + gg*8;
            *(uint4*)(sm + BHo + off) = *(const uint4*)(Bh_g + src);
            *(uint4*)(sm + BLo + off) = *(const uint4*)(Bl_g + src);
        }
        __syncthreads();

        // ---- compute: pass A=Ah x {Bh, Bl}, then A=Al x Bh ----
        #pragma unroll
        for (int pa = 0; pa < 2; pa++) {
            const uint32_t Ab = sb + (pa ? ALo : AHo);
            #pragma unroll
            for (int kk = 0; kk < 4; kk++) {
                uint32_t a0[4], a1[4];
                {
                    int row = wm*32 + (lid&7) + ((lid>>3)&1)*8;
                    int gg  = kk*2 + (lid>>4);
                    uint32_t off = (uint32_t)(row*128 + gg*16); off ^= (off>>3)&0x70;
                    ldsm4(a0, Ab + off);
                    uint32_t off2 = (uint32_t)((row+16)*128 + gg*16); off2 ^= (off2>>3)&0x70;
                    ldsm4(a1, Ab + off2);
                }
                const int krow = kk*16 + (lid&7) + ((lid>>3)&1)*8;
                #pragma unroll
                for (int np = 0; np < NP; np++) {
                    int colb = wn*WN + np*16;
                    int sbt  = colb >> 6;
                    int gg   = ((colb & 63) >> 3) + (lid>>4);
                    uint32_t off = (uint32_t)(krow*128 + gg*16); off ^= (off>>3)&0x70;
                    off += (uint32_t)sbt * 8192;
                    uint32_t b[4];
                    ldsm4t(b, sb + BHo + off);
                    mma_bf16(acc[0][np*2  ], a0, b[0], b[1]);
                    mma_bf16(acc[1][np*2  ], a1, b[0], b[1]);
                    mma_bf16(acc[0][np*2+1], a0, b[2], b[3]);
                    mma_bf16(acc[1][np*2+1], a1, b[2], b[3]);
                    if (pa == 0) {
                        uint32_t bl[4];
                        ldsm4t(bl, sb + BLo + off);
                        mma_bf16(acc[0][np*2  ], a0, bl[0], bl[1]);
                        mma_bf16(acc[1][np*2  ], a1, bl[0], bl[1]);
                        mma_bf16(acc[0][np*2+1], a0, bl[2], bl[3]);
                        mma_bf16(acc[1][np*2+1], a1, bl[2], bl[3]);
                    }
                }
            }
        }
    }

    // ---- epilogue ----
    float tval = 0.0f, dt = 0.0f, sq = 0.0f;
    if (TB)  tval = __ldg(&ts[kstep]);
    if (UPD) { float t0 = __ldg(&ts[kstep]); float t1 = __ldg(&ts[kstep+1]);
               dt = t1 - t0; sq = sqrtf(dt); }

    #pragma unroll
    for (int nt = 0; nt < NP*2; nt++) {
        const int n = n0c + wn*WN + nt*8 + (lid&3)*2;
        float2 bb = *(const float2*)(bias + n);
        float b0 = bb.x, b1 = bb.y;
        if (TB) {
            float2 w0 = *(const float2*)(W0 + n);
            b0 = fmaf(tval, w0.x, b0);
            b1 = fmaf(tval, w0.y, b1);
        }
        #pragma unroll
        for (int mt = 0; mt < 2; mt++) {
            #pragma unroll
            for (int half = 0; half < 2; half++) {
                const int m = m0 + wm*32 + mt*16 + (lid>>2) + half*8;
                float v0 = acc[mt][nt][half*2+0] + b0;
                float v1 = acc[mt][nt][half*2+1] + b1;
                if (RES) {
                    float2 r2 = *(const float2*)(resp + (size_t)m*NG + n);
                    v0 += r2.x; v1 += r2.y;
                }
                if (ACT == ACT_SWISH)    { v0 = f_swish(v0);    v1 = f_swish(v1); }
                if (ACT == ACT_SOFTPLUS) { v0 = f_softplus(v0); v1 = f_softplus(v1); }
                if (UPD) {
                    size_t idx = (size_t)m*64 + n;
                    float2 zz = *(const float2*)(Zsrc + idx);
                    float2 dd = *(const float2*)(drp  + idx);
                    float2 nn = *(const float2*)(noise + (size_t)kstep*ZSLICE + idx);
                    v0 = zz.x + dd.x*dt + v0*sq*nn.x;
                    v1 = zz.y + dd.y*dt + v1*sq*nn.y;
                }
                if (WF32)
                    *(float2*)(outF + (size_t)m*NG + n) = make_float2(v0, v1);
                if (WBF) {
                    __nv_bfloat16 h0 = __float2bfloat16(v0);
                    __nv_bfloat16 h1 = __float2bfloat16(v1);
                    __nv_bfloat16 l0 = __float2bfloat16(v0 - __bfloat162float(h0));
                    __nv_bfloat16 l1 = __float2bfloat16(v1 - __bfloat162float(h1));
                    size_t pidx = ((size_t)m*NG + n) >> 1;
                    __nv_bfloat162 hp; hp.x = h0; hp.y = h1;
                    __nv_bfloat162 lp; lp.x = l0; lp.y = l1;
                    outBh[pidx] = hp;
                    outBl[pidx] = lp;
                }
            }
        }
    }
}

// ---------------- prep: elementwise hi/lo bf16 split ----------------
__global__ void prep_split(const float* __restrict__ X, __nv_bfloat16* __restrict__ dh,
                           __nv_bfloat16* __restrict__ dl, int n)
{
    int i = blockIdx.x * 256 + threadIdx.x;
    if (i < n) {
        float v = X[i];
        __nv_bfloat16 h = __float2bfloat16(v);
        dh[i] = h;
        dl[i] = __float2bfloat16(v - __bfloat162float(h));
    }
}

// ---------------- elementwise: mu / s outputs ----------------
__global__ void latent_out_k(const float* __restrict__ lat, float* __restrict__ out)
{
    int idx = blockIdx.x * 256 + threadIdx.x;      // BATCH*LATD threads
    int row = idx >> 6;
    int j   = idx & 63;
    out[idx]             = lat[row * (2*LATD) + j];
    out[OUT_S_OFF + idx] = __expf(0.5f * lat[row * (2*LATD) + LATD + j]);
}

// ---------------------------------------------------------------------------
extern "C" void kernel_launch(void* const* d_in, const int* in_sizes, int n_in,
                              void* d_out, int out_size)
{
    const float* x     = (const float*)d_in[0];
    const float* ts    = (const float*)d_in[1];
    const float* noise = (const float*)d_in[2];
    const float* W_in  = (const float*)d_in[3];
    const float* b_in  = (const float*)d_in[4];
    const float* Wb1   = (const float*)d_in[5];
    const float* bb1   = (const float*)d_in[6];
    const float* Wb2   = (const float*)d_in[7];
    const float* bb2   = (const float*)d_in[8];
    const float* W_fo  = (const float*)d_in[9];
    const float* b_fo  = (const float*)d_in[10];
    const float* W_lat = (const float*)d_in[11];
    const float* b_lat = (const float*)d_in[12];
    const float* W_init= (const float*)d_in[13];
    const float* b_init= (const float*)d_in[14];
    const float* Wd1   = (const float*)d_in[15];
    const float* bd1   = (const float*)d_in[16];
    const float* Wd2   = (const float*)d_in[17];
    const float* bd2   = (const float*)d_in[18];
    const float* Wd3   = (const float*)d_in[19];
    const float* bd3   = (const float*)d_in[20];
    const float* Wg1   = (const float*)d_in[21];
    const float* bg1   = (const float*)d_in[22];
    const float* Wg2   = (const float*)d_in[23];
    const float* bg2   = (const float*)d_in[24];
    float* out = (float*)d_out;

    __nv_bfloat16 *xh, *xl, *ah, *al, *bh, *bl, *wh, *wl;
    float *hres, *lat, *dr;
    cudaGetSymbolAddress((void**)&xh,  g_xh);
    cudaGetSymbolAddress((void**)&xl,  g_xl);
    cudaGetSymbolAddress((void**)&ah,  g_ah);
    cudaGetSymbolAddress((void**)&al,  g_al);
    cudaGetSymbolAddress((void**)&bh,  g_bh);
    cudaGetSymbolAddress((void**)&bl,  g_bl);
    cudaGetSymbolAddress((void**)&wh,  g_wh);
    cudaGetSymbolAddress((void**)&wl,  g_wl);
    cudaGetSymbolAddress((void**)&hres,g_hres);
    cudaGetSymbolAddress((void**)&lat, g_lat);
    cudaGetSymbolAddress((void**)&dr,  g_dr);

    // ---- prep: elementwise splits (no transpose needed for mma.sync B) ----
    prep_split<<<(65536+255)/256, 256>>>(W_in, wh+OFF_WIN, wl+OFF_WIN, 65536);
    for (int i = 0; i < 3; i++) {
        prep_split<<<(65536+255)/256, 256>>>(Wb1 + (size_t)i*65536, wh+OFF_WB1+i*65536, wl+OFF_WB1+i*65536, 65536);
        prep_split<<<(65536+255)/256, 256>>>(Wb2 + (size_t)i*65536, wh+OFF_WB2+i*65536, wl+OFF_WB2+i*65536, 65536);
    }
    prep_split<<<(65536+255)/256, 256>>>(W_fo,   wh+OFF_WFO,  wl+OFF_WFO,  65536);
    prep_split<<<(32768+255)/256, 256>>>(W_lat,  wh+OFF_WLAT, wl+OFF_WLAT, 32768);
    prep_split<<<(16384+255)/256, 256>>>(W_init, wh+OFF_WINIT,wl+OFF_WINIT,16384);
    prep_split<<<(16384+255)/256, 256>>>(Wd1 + 256, wh+OFF_WD1, wl+OFF_WD1, 16384); // rows 1..64
    prep_split<<<(65536+255)/256, 256>>>(Wd2,    wh+OFF_WD2,  wl+OFF_WD2,  65536);
    prep_split<<<(16384+255)/256, 256>>>(Wd3,    wh+OFF_WD3,  wl+OFF_WD3,  16384);
    prep_split<<<(16384+255)/256, 256>>>(Wg1 + 256, wh+OFF_WG1, wl+OFF_WG1, 16384); // rows 1..64
    prep_split<<<(16384+255)/256, 256>>>(Wg2,    wh+OFF_WG2,  wl+OFF_WG2,  16384);
    prep_split<<<(BATCH*HID+255)/256, 256>>>(x, xh, xl, BATCH*HID);

    // ---- kernel handles ----
    auto* kIN  = mgemm<256,256,ACT_SWISH,   false,true, true, false,false,false>;
    auto* kB1  = mgemm<256,256,ACT_SWISH,   false,true, false,false,false,false>; // also d2
    auto* kB2  = mgemm<256,256,ACT_NONE,    true, true, true, false,false,false>;
    auto* kFO  = mgemm<256,256,ACT_NONE,    false,true, false,false,false,false>;
    auto* kLAT = mgemm<256,128,ACT_NONE,    false,false,true, false,false,false>;
    auto* kN64 = mgemm<256, 64,ACT_NONE,    false,false,true, false,false,false>; // W_init, d3
    auto* kTZ  = mgemm< 64,256,ACT_SWISH,   false,true, false,true, true, false>; // d1, g1
    auto* kG2  = mgemm<256, 64,ACT_SOFTPLUS,false,false,true, false,false,true >; // g2 + update

    const int SM128 = 32768 + 2*128*128;   // 65536
    const int SM64  = 32768 + 2*64*128;    // 49152
    cudaFuncSetAttribute((const void*)kIN,  cudaFuncAttributeMaxDynamicSharedMemorySize, SM128);
    cudaFuncSetAttribute((const void*)kB1,  cudaFuncAttributeMaxDynamicSharedMemorySize, SM128);
    cudaFuncSetAttribute((const void*)kB2,  cudaFuncAttributeMaxDynamicSharedMemorySize, SM128);
    cudaFuncSetAttribute((const void*)kFO,  cudaFuncAttributeMaxDynamicSharedMemorySize, SM128);
    cudaFuncSetAttribute((const void*)kLAT, cudaFuncAttributeMaxDynamicSharedMemorySize, SM128);
    cudaFuncSetAttribute((const void*)kN64, cudaFuncAttributeMaxDynamicSharedMemorySize, SM64);
    cudaFuncSetAttribute((const void*)kTZ,  cudaFuncAttributeMaxDynamicSharedMemorySize, SM128);
    cudaFuncSetAttribute((const void*)kG2,  cudaFuncAttributeMaxDynamicSharedMemorySize, SM64);

    dim3 blk(256);
    dim3 gN256(BATCH/128, 2);
    dim3 gN128(BATCH/128, 1);
    dim3 gN64 (BATCH/128, 1);

    __nv_bfloat162 *ah2 = (__nv_bfloat162*)ah, *al2 = (__nv_bfloat162*)al;
    __nv_bfloat162 *bh2 = (__nv_bfloat162*)bh, *bl2 = (__nv_bfloat162*)bl;

    // ---- encoder ----
    kIN<<<gN256, blk, SM128>>>(xh, xl, nullptr, wh+OFF_WIN, wl+OFF_WIN,
                               b_in, nullptr, nullptr, 0, nullptr,
                               hres, ah2, al2, nullptr, nullptr);
    for (int i = 0; i < 3; i++) {
        kB1<<<gN256, blk, SM128>>>(ah, al, nullptr,
                                   wh+OFF_WB1+i*65536, wl+OFF_WB1+i*65536,
                                   bb1 + i*HID, nullptr, nullptr, 0, nullptr,
                                   nullptr, bh2, bl2, nullptr, nullptr);
        kB2<<<gN256, blk, SM128>>>(bh, bl, nullptr,
                                   wh+OFF_WB2+i*65536, wl+OFF_WB2+i*65536,
                                   bb2 + i*HID, nullptr, nullptr, 0, hres,
                                   hres, ah2, al2, nullptr, nullptr);
    }
    kFO<<<gN256, blk, SM128>>>(ah, al, nullptr, wh+OFF_WFO, wl+OFF_WFO,
                               b_fo, nullptr, nullptr, 0, nullptr,
                               nullptr, bh2, bl2, nullptr, nullptr);
    kLAT<<<gN128, blk, SM128>>>(bh, bl, nullptr, wh+OFF_WLAT, wl+OFF_WLAT,
                                b_lat, nullptr, nullptr, 0, nullptr,
                                lat, nullptr, nullptr, nullptr, nullptr);
    latent_out_k<<<BATCH*LATD/256, blk>>>(lat, out);
    kN64<<<gN64, blk, SM64>>>(bh, bl, nullptr, wh+OFF_WINIT, wl+OFF_WINIT,
                              b_init, nullptr, nullptr, 0, nullptr,
                              out + OUT_Z_OFF, nullptr, nullptr, nullptr, nullptr);

    // ---- SDE scan ----
    for (int k = 0; k < NSTEP; k++) {
        const float* z = out + OUT_Z_OFF + (size_t)k * ZSLICE;
        // drift branch
        kTZ<<<gN256, blk, SM128>>>(nullptr, nullptr, z, wh+OFF_WD1, wl+OFF_WD1,
                                   bd1, Wd1, ts, k, nullptr,
                                   nullptr, ah2, al2, nullptr, nullptr);
        kB1<<<gN256, blk, SM128>>>(ah, al, nullptr, wh+OFF_WD2, wl+OFF_WD2,
                                   bd2, nullptr, nullptr, 0, nullptr,
                                   nullptr, bh2, bl2, nullptr, nullptr);
        kN64<<<gN64, blk, SM64>>>(bh, bl, nullptr, wh+OFF_WD3, wl+OFF_WD3,
                                  bd3, nullptr, nullptr, 0, nullptr,
                                  dr, nullptr, nullptr, nullptr, nullptr);
        // diffusion branch + fused Euler-Maruyama update
        kTZ<<<gN256, blk, SM128>>>(nullptr, nullptr, z, wh+OFF_WG1, wl+OFF_WG1,
                                   bg1, Wg1, ts, k, nullptr,
                                   nullptr, ah2, al2, nullptr, nullptr);
        kG2<<<gN64, blk, SM64>>>(ah, al, z, wh+OFF_WG2, wl+OFF_WG2,
                                 bg2, nullptr, ts, k, nullptr,
                                 out + OUT_Z_OFF + (size_t)(k+1) * ZSLICE,
                                 nullptr, nullptr, dr, noise);
    }
}

// round 4
// speedup vs baseline: 2.3040x; 1.1262x over previous
#include <cuda_runtime.h>
#include <cuda_bf16.h>
#include <stdint.h>
#include <math.h>

#define BATCH 16384
#define HID   256
#define LATD  64
#define NSTEP 63

#define OUT_S_OFF  (BATCH*LATD)
#define OUT_Z_OFF  (2*BATCH*LATD)
#define ZSLICE     (BATCH*LATD)

// ---------------- scratch (static device arrays; no allocation) ----------------
__device__ __nv_bfloat16 g_xh[BATCH*HID], g_xl[BATCH*HID];
__device__ __nv_bfloat16 g_ah[BATCH*HID], g_al[BATCH*HID];
__device__ __nv_bfloat16 g_bh[BATCH*HID], g_bl[BATCH*HID];
__device__ __nv_bfloat16 g_gh[BATCH*HID], g_gl[BATCH*HID];
__device__ float g_hres[BATCH*HID];
__device__ float g_lat [BATCH*2*LATD];

// combined [Wd1|Wg1] weights for the fused dg1 kernel: [64][512]
__device__ __nv_bfloat16 g_wdgh[64*512], g_wdgl[64*512];
__device__ float g_bdg[512], g_w0dg[512];

// weight scratch: elementwise hi/lo split, natural [K][N] layout
#define OFF_WIN   0
#define OFF_WB1   65536
#define OFF_WB2   (OFF_WB1 + 3*65536)
#define OFF_WFO   (OFF_WB2 + 3*65536)
#define OFF_WLAT  (OFF_WFO + 65536)
#define OFF_WINIT (OFF_WLAT + 32768)
#define OFF_WD2   (OFF_WINIT + 16384)
#define OFF_WD3   (OFF_WD2 + 65536)
#define OFF_WG2   (OFF_WD3 + 16384)
#define WT_TOTAL  (OFF_WG2 + 16384)

__device__ __nv_bfloat16 g_wh[WT_TOTAL];
__device__ __nv_bfloat16 g_wl[WT_TOTAL];

enum { ACT_NONE=0, ACT_SWISH=1, ACT_SOFTPLUS=2 };

__device__ __forceinline__ float f_swish(float v){
    return v * (1.0f / (1.0f + __expf(-v)));
}
__device__ __forceinline__ float f_softplus(float v){
    return fmaxf(v, 0.0f) + log1pf(__expf(-fabsf(v)));
}

__device__ __forceinline__ uint32_t smem_u32(const void* p){
    uint32_t a;
    asm("{ .reg .u64 t; cvta.to.shared.u64 t, %1; cvt.u32.u64 %0, t; }" : "=r"(a) : "l"(p));
    return a;
}
__device__ __forceinline__ void ldsm4(uint32_t (&r)[4], uint32_t addr){
    asm volatile("ldmatrix.sync.aligned.m8n8.x4.shared.b16 {%0,%1,%2,%3}, [%4];"
        : "=r"(r[0]),"=r"(r[1]),"=r"(r[2]),"=r"(r[3]) : "r"(addr));
}
__device__ __forceinline__ void ldsm4t(uint32_t (&r)[4], uint32_t addr){
    asm volatile("ldmatrix.sync.aligned.m8n8.x4.trans.shared.b16 {%0,%1,%2,%3}, [%4];"
        : "=r"(r[0]),"=r"(r[1]),"=r"(r[2]),"=r"(r[3]) : "r"(addr));
}
__device__ __forceinline__ void mma_bf16(float (&d)[4], const uint32_t (&a)[4],
                                         uint32_t b0, uint32_t b1){
    asm volatile(
        "mma.sync.aligned.m16n8k16.row.col.f32.bf16.bf16.f32 "
        "{%0,%1,%2,%3}, {%4,%5,%6,%7}, {%8,%9}, {%0,%1,%2,%3};"
        : "+f"(d[0]),"+f"(d[1]),"+f"(d[2]),"+f"(d[3])
        : "r"(a[0]),"r"(a[1]),"r"(a[2]),"r"(a[3]), "r"(b0),"r"(b1));
}
__device__ __forceinline__ void cpa16(uint32_t dst, const void* src){
    asm volatile("cp.async.cg.shared.global [%0], [%1], 16;" :: "r"(dst), "l"(src));
}
#define CP_COMMIT() asm volatile("cp.async.commit_group;" ::: "memory")
#define CP_WAIT(n)  asm volatile("cp.async.wait_group %0;" :: "n"(n) : "memory")

// ---------------------------------------------------------------------------
// (encoder) mma.sync bf16 split GEMM — same as R3.
// ---------------------------------------------------------------------------
template<int K, int NG, int ACT, bool RES, bool WBF, bool WF32>
__global__ void __launch_bounds__(256,2) mgemm(
    const __nv_bfloat16* __restrict__ Ah_g, const __nv_bfloat16* __restrict__ Al_g,
    const __nv_bfloat16* __restrict__ Bh_g, const __nv_bfloat16* __restrict__ Bl_g,
    const float* __restrict__ bias,
    const float* __restrict__ resp,
    float* __restrict__ outF,
    __nv_bfloat162* __restrict__ outBh, __nv_bfloat162* __restrict__ outBl)
{
    constexpr int BN  = (NG >= 128) ? 128 : 64;
    constexpr int WN  = BN / 2;
    constexpr int NP  = WN / 16;
    constexpr int NCH = K / 64;
    constexpr int BSZ = BN * 128;
    constexpr int AHo = 0, ALo = 16384, BHo = 32768, BLo = 32768 + BSZ;

    extern __shared__ char sm[];
    const int tid = threadIdx.x;
    const int lid = tid & 31, wid = tid >> 5;
    const int wm  = wid & 3;
    const int wn  = wid >> 2;
    const int m0  = blockIdx.x * 128;
    const int n0c = blockIdx.y * BN;
    const uint32_t sb = smem_u32(sm);

    float acc[2][NP*2][4];
    #pragma unroll
    for (int i=0;i<2;i++)
        #pragma unroll
        for (int j=0;j<NP*2;j++)
            #pragma unroll
            for (int q=0;q<4;q++) acc[i][j][q] = 0.0f;

    for (int c = 0; c < NCH; c++) {
        const int c64 = c * 64;
        if (c) __syncthreads();

        #pragma unroll
        for (int it = 0; it < 4; it++) {
            int g = tid + it*256;
            int row = g >> 3, gg = g & 7;
            uint32_t off = (uint32_t)(row*128 + gg*16);
            off ^= (off >> 3) & 0x70;
            size_t src = (size_t)(m0+row)*K + c64 + gg*8;
            *(uint4*)(sm + AHo + off) = *(const uint4*)(Ah_g + src);
            *(uint4*)(sm + ALo + off) = *(const uint4*)(Al_g + src);
        }
        #pragma unroll
        for (int it = 0; it < BN/32; it++) {
            int g = tid + it*256;
            int row, gg;
            if (BN == 128) { row = g >> 4; gg = g & 15; }
            else           { row = g >> 3; gg = g & 7;  }
            int s = gg >> 3, gin = gg & 7;
            uint32_t off = (uint32_t)(row*128 + gin*16);
            off ^= (off >> 3) & 0x70;
            off += (uint32_t)s * 8192;
            size_t src = (size_t)(c64+row)*NG + n0c + gg*8;
            *(uint4*)(sm + BHo + off) = *(const uint4*)(Bh_g + src);
            *(uint4*)(sm + BLo + off) = *(const uint4*)(Bl_g + src);
        }
        __syncthreads();

        #pragma unroll
        for (int pa = 0; pa < 2; pa++) {
            const uint32_t Ab = sb + (pa ? ALo : AHo);
            #pragma unroll
            for (int kk = 0; kk < 4; kk++) {
                uint32_t a0[4], a1[4];
                {
                    int row = wm*32 + (lid&7) + ((lid>>3)&1)*8;
                    int gg  = kk*2 + (lid>>4);
                    uint32_t off = (uint32_t)(row*128 + gg*16); off ^= (off>>3)&0x70;
                    ldsm4(a0, Ab + off);
                    uint32_t off2 = (uint32_t)((row+16)*128 + gg*16); off2 ^= (off2>>3)&0x70;
                    ldsm4(a1, Ab + off2);
                }
                const int krow = kk*16 + (lid&7) + ((lid>>3)&1)*8;
                #pragma unroll
                for (int np = 0; np < NP; np++) {
                    int colb = wn*WN + np*16;
                    int sbt  = colb >> 6;
                    int gg   = ((colb & 63) >> 3) + (lid>>4);
                    uint32_t off = (uint32_t)(krow*128 + gg*16); off ^= (off>>3)&0x70;
                    off += (uint32_t)sbt * 8192;
                    uint32_t b[4];
                    ldsm4t(b, sb + BHo + off);
                    mma_bf16(acc[0][np*2  ], a0, b[0], b[1]);
                    mma_bf16(acc[1][np*2  ], a1, b[0], b[1]);
                    mma_bf16(acc[0][np*2+1], a0, b[2], b[3]);
                    mma_bf16(acc[1][np*2+1], a1, b[2], b[3]);
                    if (pa == 0) {
                        uint32_t bl[4];
                        ldsm4t(bl, sb + BLo + off);
                        mma_bf16(acc[0][np*2  ], a0, bl[0], bl[1]);
                        mma_bf16(acc[1][np*2  ], a1, bl[0], bl[1]);
                        mma_bf16(acc[0][np*2+1], a0, bl[2], bl[3]);
                        mma_bf16(acc[1][np*2+1], a1, bl[2], bl[3]);
                    }
                }
            }
        }
    }

    #pragma unroll
    for (int nt = 0; nt < NP*2; nt++) {
        const int n = n0c + wn*WN + nt*8 + (lid&3)*2;
        float2 bb = *(const float2*)(bias + n);
        float b0 = bb.x, b1 = bb.y;
        #pragma unroll
        for (int mt = 0; mt < 2; mt++) {
            #pragma unroll
            for (int half = 0; half < 2; half++) {
                const int m = m0 + wm*32 + mt*16 + (lid>>2) + half*8;
                float v0 = acc[mt][nt][half*2+0] + b0;
                float v1 = acc[mt][nt][half*2+1] + b1;
                if (RES) {
                    float2 r2 = *(const float2*)(resp + (size_t)m*NG + n);
                    v0 += r2.x; v1 += r2.y;
                }
                if (ACT == ACT_SWISH)    { v0 = f_swish(v0);    v1 = f_swish(v1); }
                if (WF32)
                    *(float2*)(outF + (size_t)m*NG + n) = make_float2(v0, v1);
                if (WBF) {
                    __nv_bfloat16 h0 = __float2bfloat16(v0);
                    __nv_bfloat16 h1 = __float2bfloat16(v1);
                    __nv_bfloat16 l0 = __float2bfloat16(v0 - __bfloat162float(h0));
                    __nv_bfloat16 l1 = __float2bfloat16(v1 - __bfloat162float(h1));
                    size_t pidx = ((size_t)m*NG + n) >> 1;
                    __nv_bfloat162 hp; hp.x = h0; hp.y = h1;
                    __nv_bfloat162 lp; lp.x = l0; lp.y = l1;
                    outBh[pidx] = hp;
                    outBl[pidx] = lp;
                }
            }
        }
    }
}

// ---------------------------------------------------------------------------
// SCAN kernel 1: fused d1+g1.  C[M,512] = swish(z@[Wd1|Wg1] + (b + t*W0))
// K=64 single chunk; A built on-the-fly from f32 z; BN=128, grid (128,4).
// Cols [0,256) -> drift h1 (ah/al), cols [256,512) -> diffusion h1 (gh/gl).
// ---------------------------------------------------------------------------
__global__ void __launch_bounds__(256,2) dg1_k(
    const float* __restrict__ Zsrc,
    const __nv_bfloat16* __restrict__ Bh_g, const __nv_bfloat16* __restrict__ Bl_g,
    const float* __restrict__ bias512, const float* __restrict__ w0512,
    const float* __restrict__ ts, int kstep,
    __nv_bfloat162* __restrict__ outDh, __nv_bfloat162* __restrict__ outDl,
    __nv_bfloat162* __restrict__ outGh, __nv_bfloat162* __restrict__ outGl)
{
    constexpr int NG = 512;
    constexpr int AHo=0, ALo=16384, BHo=32768, BLo=49152;
    extern __shared__ char sm[];
    const int tid=threadIdx.x, lid=tid&31, wid=tid>>5;
    const int wm=wid&3, wn=wid>>2;
    const int m0 = blockIdx.x*128;
    const int n0c = blockIdx.y*128;
    const uint32_t sb = smem_u32(sm);

    float acc[2][8][4];
    #pragma unroll
    for (int i=0;i<2;i++)
        #pragma unroll
        for (int j=0;j<8;j++)
            #pragma unroll
            for (int q=0;q<4;q++) acc[i][j][q]=0.0f;

    // A from z (f32 -> hi/lo)
    #pragma unroll
    for (int it = 0; it < 4; it++) {
        int g = tid + it*256;
        int row = g >> 3, gg = g & 7;
        uint32_t off = (uint32_t)(row*128 + gg*16);
        off ^= (off >> 3) & 0x70;
        const float* zp = Zsrc + (size_t)(m0+row)*64 + gg*8;
        float4 f0 = *(const float4*)zp;
        float4 f1 = *(const float4*)(zp+4);
        float fv[8] = {f0.x,f0.y,f0.z,f0.w,f1.x,f1.y,f1.z,f1.w};
        alignas(16) __nv_bfloat16 hv[8], lv[8];
        #pragma unroll
        for (int j=0;j<8;j++){
            __nv_bfloat16 h = __float2bfloat16(fv[j]);
            hv[j]=h; lv[j]=__float2bfloat16(fv[j]-__bfloat162float(h));
        }
        *(uint4*)(sm + AHo + off) = *(const uint4*)hv;
        *(uint4*)(sm + ALo + off) = *(const uint4*)lv;
    }
    // B: 64 rows x 128 cols of [64][512]
    #pragma unroll
    for (int it = 0; it < 4; it++) {
        int g = tid + it*256;
        int row = g >> 4, gg = g & 15;
        int sbt = gg >> 3, gin = gg & 7;
        uint32_t off = (uint32_t)(row*128 + gin*16);
        off ^= (off >> 3) & 0x70;
        off += (uint32_t)sbt * 8192;
        size_t src = (size_t)row*NG + n0c + gg*8;
        *(uint4*)(sm + BHo + off) = *(const uint4*)(Bh_g + src);
        *(uint4*)(sm + BLo + off) = *(const uint4*)(Bl_g + src);
    }
    __syncthreads();

    #pragma unroll
    for (int pa = 0; pa < 2; pa++) {
        const uint32_t Ab = sb + (pa ? ALo : AHo);
        #pragma unroll
        for (int kk = 0; kk < 4; kk++) {
            uint32_t a0[4], a1[4];
            {
                int row = wm*32 + (lid&7) + ((lid>>3)&1)*8;
                int gg  = kk*2 + (lid>>4);
                uint32_t off = (uint32_t)(row*128 + gg*16); off ^= (off>>3)&0x70;
                ldsm4(a0, Ab + off);
                uint32_t off2 = (uint32_t)((row+16)*128 + gg*16); off2 ^= (off2>>3)&0x70;
                ldsm4(a1, Ab + off2);
            }
            const int krow = kk*16 + (lid&7) + ((lid>>3)&1)*8;
            #pragma unroll
            for (int np = 0; np < 4; np++) {
                int colb = wn*64 + np*16;
                int sbt  = colb >> 6;
                int gg   = ((colb & 63) >> 3) + (lid>>4);
                uint32_t off = (uint32_t)(krow*128 + gg*16); off ^= (off>>3)&0x70;
                off += (uint32_t)sbt * 8192;
                uint32_t b[4];
                ldsm4t(b, sb + BHo + off);
                mma_bf16(acc[0][np*2  ], a0, b[0], b[1]);
                mma_bf16(acc[1][np*2  ], a1, b[0], b[1]);
                mma_bf16(acc[0][np*2+1], a0, b[2], b[3]);
                mma_bf16(acc[1][np*2+1], a1, b[2], b[3]);
                if (pa == 0) {
                    uint32_t bl[4];
                    ldsm4t(bl, sb + BLo + off);
                    mma_bf16(acc[0][np*2  ], a0, bl[0], bl[1]);
                    mma_bf16(acc[1][np*2  ], a1, bl[0], bl[1]);
                    mma_bf16(acc[0][np*2+1], a0, bl[2], bl[3]);
                    mma_bf16(acc[1][np*2+1], a1, bl[2], bl[3]);
                }
            }
        }
    }

    const bool isg = (n0c >= 256);
    __nv_bfloat162* oh = isg ? outGh : outDh;
    __nv_bfloat162* ol = isg ? outGl : outDl;
    const int nsub = isg ? 256 : 0;
    const float tval = __ldg(&ts[kstep]);

    #pragma unroll
    for (int nt = 0; nt < 8; nt++) {
        const int n = n0c + wn*64 + nt*8 + (lid&3)*2;
        float2 bb = *(const float2*)(bias512 + n);
        float2 w0 = *(const float2*)(w0512 + n);
        float b0 = fmaf(tval, w0.x, bb.x);
        float b1 = fmaf(tval, w0.y, bb.y);
        #pragma unroll
        for (int mt = 0; mt < 2; mt++) {
            #pragma unroll
            for (int half = 0; half < 2; half++) {
                const int m = m0 + wm*32 + mt*16 + (lid>>2) + half*8;
                float v0 = f_swish(acc[mt][nt][half*2+0] + b0);
                float v1 = f_swish(acc[mt][nt][half*2+1] + b1);
                __nv_bfloat16 h0 = __float2bfloat16(v0);
                __nv_bfloat16 h1 = __float2bfloat16(v1);
                __nv_bfloat16 l0 = __float2bfloat16(v0 - __bfloat162float(h0));
                __nv_bfloat16 l1 = __float2bfloat16(v1 - __bfloat162float(h1));
                size_t pidx = ((size_t)m*256 + (n - nsub)) >> 1;
                __nv_bfloat162 hp; hp.x = h0; hp.y = h1;
                __nv_bfloat162 lp; lp.x = l0; lp.y = l1;
                oh[pidx] = hp;
                ol[pidx] = lp;
            }
        }
    }
}

// ---------------------------------------------------------------------------
// SCAN kernel 2: d2 = swish(h1@Wd2 + bd2). K=256, BN=256 per CTA (grid 128),
// 2-stage cp.async double-buffered pipeline (192 KB smem).
// ---------------------------------------------------------------------------
__global__ void __launch_bounds__(256,1) d2_k(
    const __nv_bfloat16* __restrict__ Ah_g, const __nv_bfloat16* __restrict__ Al_g,
    const __nv_bfloat16* __restrict__ Bh_g, const __nv_bfloat16* __restrict__ Bl_g,
    const float* __restrict__ bias,
    __nv_bfloat162* __restrict__ outBh, __nv_bfloat162* __restrict__ outBl)
{
    constexpr int K=256, NG=256;
    constexpr int SST = 98304;
    constexpr int AHo=0, ALo=16384, BHo=32768, BLo=65536;
    extern __shared__ char sm[];
    const int tid=threadIdx.x, lid=tid&31, wid=tid>>5;
    const int wm=wid&3, wn=wid>>2;
    const int m0 = blockIdx.x*128;
    const uint32_t sb = smem_u32(sm);

    float acc[2][16][4];
    #pragma unroll
    for (int i=0;i<2;i++)
        #pragma unroll
        for (int j=0;j<16;j++)
            #pragma unroll
            for (int q=0;q<4;q++) acc[i][j][q]=0.0f;

    auto load_chunk = [&](int c, int s){
        const uint32_t stb = sb + (uint32_t)s*SST;
        const int c64 = c*64;
        #pragma unroll
        for (int it=0; it<4; it++){
            int g = tid + it*256;
            int row = g>>3, gg = g&7;
            uint32_t off = (uint32_t)(row*128 + gg*16); off ^= (off>>3)&0x70;
            size_t src = (size_t)(m0+row)*K + c64 + gg*8;
            cpa16(stb + AHo + off, Ah_g + src);
            cpa16(stb + ALo + off, Al_g + src);
        }
        #pragma unroll
        for (int it=0; it<8; it++){
            int g = tid + it*256;
            int row = g>>5, gg = g&31;
            int sbt = gg>>3, gin = gg&7;
            uint32_t off = (uint32_t)(row*128 + gin*16); off ^= (off>>3)&0x70;
            off += (uint32_t)sbt*8192;
            size_t src = (size_t)(c64+row)*NG + gg*8;
            cpa16(stb + BHo + off, Bh_g + src);
            cpa16(stb + BLo + off, Bl_g + src);
        }
        CP_COMMIT();
    };

    load_chunk(0, 0);
    for (int c = 0; c < 4; c++) {
        if (c+1 < 4) { load_chunk(c+1, (c+1)&1); CP_WAIT(1); }
        else         { CP_WAIT(0); }
        __syncthreads();
        const uint32_t stb = sb + (uint32_t)(c&1)*SST;
        #pragma unroll
        for (int pa = 0; pa < 2; pa++) {
            const uint32_t Ab = stb + (pa ? ALo : AHo);
            #pragma unroll
            for (int kk = 0; kk < 4; kk++) {
                uint32_t a0[4], a1[4];
                {
                    int row = wm*32 + (lid&7) + ((lid>>3)&1)*8;
                    int gg  = kk*2 + (lid>>4);
                    uint32_t off = (uint32_t)(row*128 + gg*16); off ^= (off>>3)&0x70;
                    ldsm4(a0, Ab + off);
                    uint32_t off2 = (uint32_t)((row+16)*128 + gg*16); off2 ^= (off2>>3)&0x70;
                    ldsm4(a1, Ab + off2);
                }
                const int krow = kk*16 + (lid&7) + ((lid>>3)&1)*8;
                #pragma unroll
                for (int np = 0; np < 8; np++) {
                    int colb = wn*128 + np*16;
                    int sbt  = colb >> 6;
                    int gg   = ((colb & 63) >> 3) + (lid>>4);
                    uint32_t off = (uint32_t)(krow*128 + gg*16); off ^= (off>>3)&0x70;
                    off += (uint32_t)sbt * 8192;
                    uint32_t b[4];
                    ldsm4t(b, stb + BHo + off);
                    mma_bf16(acc[0][np*2  ], a0, b[0], b[1]);
                    mma_bf16(acc[1][np*2  ], a1, b[0], b[1]);
                    mma_bf16(acc[0][np*2+1], a0, b[2], b[3]);
                    mma_bf16(acc[1][np*2+1], a1, b[2], b[3]);
                    if (pa == 0) {
                        uint32_t bl[4];
                        ldsm4t(bl, stb + BLo + off);
                        mma_bf16(acc[0][np*2  ], a0, bl[0], bl[1]);
                        mma_bf16(acc[1][np*2  ], a1, bl[0], bl[1]);
                        mma_bf16(acc[0][np*2+1], a0, bl[2], bl[3]);
                        mma_bf16(acc[1][np*2+1], a1, bl[2], bl[3]);
                    }
                }
            }
        }
        __syncthreads();
    }

    #pragma unroll
    for (int nt = 0; nt < 16; nt++) {
        const int n = wn*128 + nt*8 + (lid&3)*2;
        float2 bb = *(const float2*)(bias + n);
        #pragma unroll
        for (int mt = 0; mt < 2; mt++) {
            #pragma unroll
            for (int half = 0; half < 2; half++) {
                const int m = m0 + wm*32 + mt*16 + (lid>>2) + half*8;
                float v0 = f_swish(acc[mt][nt][half*2+0] + bb.x);
                float v1 = f_swish(acc[mt][nt][half*2+1] + bb.y);
                __nv_bfloat16 h0 = __float2bfloat16(v0);
                __nv_bfloat16 h1 = __float2bfloat16(v1);
                __nv_bfloat16 l0 = __float2bfloat16(v0 - __bfloat162float(h0));
                __nv_bfloat16 l1 = __float2bfloat16(v1 - __bfloat162float(h1));
                size_t pidx = ((size_t)m*NG + n) >> 1;
                __nv_bfloat162 hp; hp.x = h0; hp.y = h1;
                __nv_bfloat162 lp; lp.x = l0; lp.y = l1;
                outBh[pidx] = hp;
                outBl[pidx] = lp;
            }
        }
    }
}

// ---------------------------------------------------------------------------
// SCAN kernel 3: d3 + g2 + Euler-Maruyama update.
// dr = h2@Wd3 + bd3 ; df = softplus(h1g@Wg2 + bg2)
// z_new = z + dr*dt + df*sqrt(dt)*noise -> z_path[k+1]
// Both GEMMs K=256, N=64; 8 pipelined chunks (2-stage cp.async, 96 KB smem).
// ---------------------------------------------------------------------------
__device__ __forceinline__ void compute_np2(
    float (&acc)[2][4][4], uint32_t stb, int wm, int wn, int lid)
{
    #pragma unroll
    for (int pa = 0; pa < 2; pa++) {
        const uint32_t Ab = stb + (pa ? 16384u : 0u);
        #pragma unroll
        for (int kk = 0; kk < 4; kk++) {
            uint32_t a0[4], a1[4];
            {
                int row = wm*32 + (lid&7) + ((lid>>3)&1)*8;
                int gg  = kk*2 + (lid>>4);
                uint32_t off = (uint32_t)(row*128 + gg*16); off ^= (off>>3)&0x70;
                ldsm4(a0, Ab + off);
                uint32_t off2 = (uint32_t)((row+16)*128 + gg*16); off2 ^= (off2>>3)&0x70;
                ldsm4(a1, Ab + off2);
            }
            const int krow = kk*16 + (lid&7) + ((lid>>3)&1)*8;
            #pragma unroll
            for (int np = 0; np < 2; np++) {
                int colb = wn*32 + np*16;
                int gg   = (colb >> 3) + (lid>>4);
                uint32_t off = (uint32_t)(krow*128 + gg*16); off ^= (off>>3)&0x70;
                uint32_t b[4];
                ldsm4t(b, stb + 32768u + off);
                mma_bf16(acc[0][np*2  ], a0, b[0], b[1]);
                mma_bf16(acc[1][np*2  ], a1, b[0], b[1]);
                mma_bf16(acc[0][np*2+1], a0, b[2], b[3]);
                mma_bf16(acc[1][np*2+1], a1, b[2], b[3]);
                if (pa == 0) {
                    uint32_t bl[4];
                    ldsm4t(bl, stb + 40960u + off);
                    mma_bf16(acc[0][np*2  ], a0, bl[0], bl[1]);
                    mma_bf16(acc[1][np*2  ], a1, bl[0], bl[1]);
                    mma_bf16(acc[0][np*2+1], a0, bl[2], bl[3]);
                    mma_bf16(acc[1][np*2+1], a1, bl[2], bl[3]);
                }
            }
        }
    }
}

__global__ void __launch_bounds__(256,1) d3g2_k(
    const __nv_bfloat16* __restrict__ Hh, const __nv_bfloat16* __restrict__ Hl,   // h2
    const __nv_bfloat16* __restrict__ Gh, const __nv_bfloat16* __restrict__ Gl,   // g1
    const __nv_bfloat16* __restrict__ Wd3h, const __nv_bfloat16* __restrict__ Wd3l,
    const __nv_bfloat16* __restrict__ Wg2h, const __nv_bfloat16* __restrict__ Wg2l,
    const float* __restrict__ bd3, const float* __restrict__ bg2,
    const float* __restrict__ Zsrc, const float* __restrict__ ts, int kstep,
    const float* __restrict__ noise, float* __restrict__ zout)
{
    constexpr int SST = 49152;
    extern __shared__ char sm[];
    const int tid=threadIdx.x, lid=tid&31, wid=tid>>5;
    const int wm=wid&3, wn=wid>>2;
    const int m0 = blockIdx.x*128;
    const uint32_t sb = smem_u32(sm);

    float accD[2][4][4], accG[2][4][4];
    #pragma unroll
    for (int i=0;i<2;i++)
        #pragma unroll
        for (int j=0;j<4;j++)
            #pragma unroll
            for (int q=0;q<4;q++){ accD[i][j][q]=0.0f; accG[i][j][q]=0.0f; }

    auto load_chunk = [&](int cc, int s){
        const int phase = cc >> 2, c = cc & 3, c64 = c*64;
        const __nv_bfloat16* Ah = phase ? Gh : Hh;
        const __nv_bfloat16* Al = phase ? Gl : Hl;
        const __nv_bfloat16* Bh = phase ? Wg2h : Wd3h;
        const __nv_bfloat16* Bl = phase ? Wg2l : Wd3l;
        const uint32_t stb = sb + (uint32_t)s*SST;
        #pragma unroll
        for (int it=0; it<4; it++){
            int g = tid + it*256;
            int row = g>>3, gg = g&7;
            uint32_t off = (uint32_t)(row*128 + gg*16); off ^= (off>>3)&0x70;
            size_t src = (size_t)(m0+row)*256 + c64 + gg*8;
            cpa16(stb + 0     + off, Ah + src);
            cpa16(stb + 16384 + off, Al + src);
        }
        #pragma unroll
        for (int it=0; it<2; it++){
            int g = tid + it*256;
            int row = g>>3, gg = g&7;
            uint32_t off = (uint32_t)(row*128 + gg*16); off ^= (off>>3)&0x70;
            size_t src = (size_t)(c64+row)*64 + gg*8;
            cpa16(stb + 32768 + off, Bh + src);
            cpa16(stb + 40960 + off, Bl + src);
        }
        CP_COMMIT();
    };

    load_chunk(0, 0);
    for (int cc = 0; cc < 8; cc++) {
        if (cc+1 < 8) { load_chunk(cc+1, (cc+1)&1); CP_WAIT(1); }
        else          { CP_WAIT(0); }
        __syncthreads();
        const uint32_t stb = sb + (uint32_t)(cc&1)*SST;
        if (cc < 4) compute_np2(accD, stb, wm, wn, lid);
        else        compute_np2(accG, stb, wm, wn, lid);
        __syncthreads();
    }

    const float t0 = __ldg(&ts[kstep]);
    const float t1 = __ldg(&ts[kstep+1]);
    const float dt = t1 - t0;
    const float sq = sqrtf(dt);

    #pragma unroll
    for (int nt = 0; nt < 4; nt++) {
        const int n = wn*32 + nt*8 + (lid&3)*2;
        float2 bd = *(const float2*)(bd3 + n);
        float2 bg = *(const float2*)(bg2 + n);
        #pragma unroll
        for (int mt = 0; mt < 2; mt++) {
            #pragma unroll
            for (int half = 0; half < 2; half++) {
                const int m = m0 + wm*32 + mt*16 + (lid>>2) + half*8;
                float d0 = accD[mt][nt][half*2+0] + bd.x;
                float d1 = accD[mt][nt][half*2+1] + bd.y;
                float g0 = f_softplus(accG[mt][nt][half*2+0] + bg.x);
                float g1 = f_softplus(accG[mt][nt][half*2+1] + bg.y);
                size_t idx = (size_t)m*64 + n;
                float2 zz = *(const float2*)(Zsrc + idx);
                float2 nn = *(const float2*)(noise + (size_t)kstep*ZSLICE + idx);
                float z0 = zz.x + d0*dt + g0*sq*nn.x;
                float z1 = zz.y + d1*dt + g1*sq*nn.y;
                *(float2*)(zout + idx) = make_float2(z0, z1);
            }
        }
    }
}

// ---------------- prep kernels ----------------
__global__ void prep_split(const float* __restrict__ X, __nv_bfloat16* __restrict__ dh,
                           __nv_bfloat16* __restrict__ dl, int n)
{
    int i = blockIdx.x * 256 + threadIdx.x;
    if (i < n) {
        float v = X[i];
        __nv_bfloat16 h = __float2bfloat16(v);
        dh[i] = h;
        dl[i] = __float2bfloat16(v - __bfloat162float(h));
    }
}

__global__ void prep_dg1(const float* __restrict__ Wd1, const float* __restrict__ Wg1,
                         const float* __restrict__ bd1, const float* __restrict__ bg1,
                         __nv_bfloat16* __restrict__ wh, __nv_bfloat16* __restrict__ wl,
                         float* __restrict__ bias, float* __restrict__ w0)
{
    int idx = blockIdx.x * 256 + threadIdx.x;   // 64*512
    int k = idx >> 9, n = idx & 511;
    float v = (n < 256) ? Wd1[(size_t)(k+1)*256 + n] : Wg1[(size_t)(k+1)*256 + (n-256)];
    __nv_bfloat16 h = __float2bfloat16(v);
    wh[idx] = h;
    wl[idx] = __float2bfloat16(v - __bfloat162float(h));
    if (idx < 512) {
        bias[idx] = (idx < 256) ? bd1[idx] : bg1[idx-256];
        w0[idx]   = (idx < 256) ? Wd1[idx] : Wg1[idx-256];
    }
}

// ---------------- elementwise: mu / s outputs ----------------
__global__ void latent_out_k(const float* __restrict__ lat, float* __restrict__ out)
{
    int idx = blockIdx.x * 256 + threadIdx.x;
    int row = idx >> 6;
    int j   = idx & 63;
    out[idx]             = lat[row * (2*LATD) + j];
    out[OUT_S_OFF + idx] = __expf(0.5f * lat[row * (2*LATD) + LATD + j]);
}

// ---------------------------------------------------------------------------
extern "C" void kernel_launch(void* const* d_in, const int* in_sizes, int n_in,
                              void* d_out, int out_size)
{
    const float* x     = (const float*)d_in[0];
    const float* ts    = (const float*)d_in[1];
    const float* noise = (const float*)d_in[2];
    const float* W_in  = (const float*)d_in[3];
    const float* b_in  = (const float*)d_in[4];
    const float* Wb1   = (const float*)d_in[5];
    const float* bb1   = (const float*)d_in[6];
    const float* Wb2   = (const float*)d_in[7];
    const float* bb2   = (const float*)d_in[8];
    const float* W_fo  = (const float*)d_in[9];
    const float* b_fo  = (const float*)d_in[10];
    const float* W_lat = (const float*)d_in[11];
    const float* b_lat = (const float*)d_in[12];
    const float* W_init= (const float*)d_in[13];
    const float* b_init= (const float*)d_in[14];
    const float* Wd1   = (const float*)d_in[15];
    const float* bd1   = (const float*)d_in[16];
    const float* Wd2   = (const float*)d_in[17];
    const float* bd2   = (const float*)d_in[18];
    const float* Wd3   = (const float*)d_in[19];
    const float* bd3   = (const float*)d_in[20];
    const float* Wg1   = (const float*)d_in[21];
    const float* bg1   = (const float*)d_in[22];
    const float* Wg2   = (const float*)d_in[23];
    const float* bg2   = (const float*)d_in[24];
    float* out = (float*)d_out;

    __nv_bfloat16 *xh, *xl, *ah, *al, *bh, *bl, *gh, *gl, *wh, *wl, *wdgh, *wdgl;
    float *hres, *lat, *bdg, *w0dg;
    cudaGetSymbolAddress((void**)&xh,  g_xh);
    cudaGetSymbolAddress((void**)&xl,  g_xl);
    cudaGetSymbolAddress((void**)&ah,  g_ah);
    cudaGetSymbolAddress((void**)&al,  g_al);
    cudaGetSymbolAddress((void**)&bh,  g_bh);
    cudaGetSymbolAddress((void**)&bl,  g_bl);
    cudaGetSymbolAddress((void**)&gh,  g_gh);
    cudaGetSymbolAddress((void**)&gl,  g_gl);
    cudaGetSymbolAddress((void**)&wh,  g_wh);
    cudaGetSymbolAddress((void**)&wl,  g_wl);
    cudaGetSymbolAddress((void**)&wdgh,g_wdgh);
    cudaGetSymbolAddress((void**)&wdgl,g_wdgl);
    cudaGetSymbolAddress((void**)&hres,g_hres);
    cudaGetSymbolAddress((void**)&lat, g_lat);
    cudaGetSymbolAddress((void**)&bdg, g_bdg);
    cudaGetSymbolAddress((void**)&w0dg,g_w0dg);

    // ---- prep ----
    prep_split<<<256, 256>>>(W_in, wh+OFF_WIN, wl+OFF_WIN, 65536);
    for (int i = 0; i < 3; i++) {
        prep_split<<<256, 256>>>(Wb1 + (size_t)i*65536, wh+OFF_WB1+i*65536, wl+OFF_WB1+i*65536, 65536);
        prep_split<<<256, 256>>>(Wb2 + (size_t)i*65536, wh+OFF_WB2+i*65536, wl+OFF_WB2+i*65536, 65536);
    }
    prep_split<<<256, 256>>>(W_fo,   wh+OFF_WFO,  wl+OFF_WFO,  65536);
    prep_split<<<128, 256>>>(W_lat,  wh+OFF_WLAT, wl+OFF_WLAT, 32768);
    prep_split<<<64,  256>>>(W_init, wh+OFF_WINIT,wl+OFF_WINIT,16384);
    prep_split<<<256, 256>>>(Wd2,    wh+OFF_WD2,  wl+OFF_WD2,  65536);
    prep_split<<<64,  256>>>(Wd3,    wh+OFF_WD3,  wl+OFF_WD3,  16384);
    prep_split<<<64,  256>>>(Wg2,    wh+OFF_WG2,  wl+OFF_WG2,  16384);
    prep_dg1  <<<128, 256>>>(Wd1, Wg1, bd1, bg1, wdgh, wdgl, bdg, w0dg);
    prep_split<<<BATCH*HID/256, 256>>>(x, xh, xl, BATCH*HID);

    // ---- encoder kernel handles ----
    auto* kIN  = mgemm<256,256,ACT_SWISH, false,true, true >;
    auto* kB1  = mgemm<256,256,ACT_SWISH, false,true, false>;
    auto* kB2  = mgemm<256,256,ACT_NONE,  true, true, true >;
    auto* kFO  = mgemm<256,256,ACT_NONE,  false,true, false>;
    auto* kLAT = mgemm<256,128,ACT_NONE,  false,false,true >;
    auto* kN64 = mgemm<256, 64,ACT_NONE,  false,false,true >;

    const int SM128 = 32768 + 2*128*128;   // 65536
    const int SM64  = 32768 + 2*64*128;    // 49152
    cudaFuncSetAttribute((const void*)kIN,  cudaFuncAttributeMaxDynamicSharedMemorySize, SM128);
    cudaFuncSetAttribute((const void*)kB1,  cudaFuncAttributeMaxDynamicSharedMemorySize, SM128);
    cudaFuncSetAttribute((const void*)kB2,  cudaFuncAttributeMaxDynamicSharedMemorySize, SM128);
    cudaFuncSetAttribute((const void*)kFO,  cudaFuncAttributeMaxDynamicSharedMemorySize, SM128);
    cudaFuncSetAttribute((const void*)kLAT, cudaFuncAttributeMaxDynamicSharedMemorySize, SM128);
    cudaFuncSetAttribute((const void*)kN64, cudaFuncAttributeMaxDynamicSharedMemorySize, SM64);
    cudaFuncSetAttribute((const void*)dg1_k, cudaFuncAttributeMaxDynamicSharedMemorySize, 65536);
    cudaFuncSetAttribute((const void*)d2_k,  cudaFuncAttributeMaxDynamicSharedMemorySize, 196608);
    cudaFuncSetAttribute((const void*)d3g2_k,cudaFuncAttributeMaxDynamicSharedMemorySize, 98304);

    dim3 blk(256);
    dim3 gN256(BATCH/128, 2);
    dim3 gN128(BATCH/128, 1);

    __nv_bfloat162 *ah2 = (__nv_bfloat162*)ah, *al2 = (__nv_bfloat162*)al;
    __nv_bfloat162 *bh2 = (__nv_bfloat162*)bh, *bl2 = (__nv_bfloat162*)bl;
    __nv_bfloat162 *gh2 = (__nv_bfloat162*)gh, *gl2 = (__nv_bfloat162*)gl;

    // ---- encoder ----
    kIN<<<gN256, blk, SM128>>>(xh, xl, wh+OFF_WIN, wl+OFF_WIN, b_in,
                               nullptr, hres, ah2, al2);
    for (int i = 0; i < 3; i++) {
        kB1<<<gN256, blk, SM128>>>(ah, al, wh+OFF_WB1+i*65536, wl+OFF_WB1+i*65536,
                                   bb1 + i*HID, nullptr, nullptr, bh2, bl2);
        kB2<<<gN256, blk, SM128>>>(bh, bl, wh+OFF_WB2+i*65536, wl+OFF_WB2+i*65536,
                                   bb2 + i*HID, hres, hres, ah2, al2);
    }
    kFO<<<gN256, blk, SM128>>>(ah, al, wh+OFF_WFO, wl+OFF_WFO, b_fo,
                               nullptr, nullptr, bh2, bl2);
    kLAT<<<gN128, blk, SM128>>>(bh, bl, wh+OFF_WLAT, wl+OFF_WLAT, b_lat,
                                nullptr, lat, nullptr, nullptr);
    latent_out_k<<<BATCH*LATD/256, blk>>>(lat, out);
    kN64<<<gN128, blk, SM64>>>(bh, bl, wh+OFF_WINIT, wl+OFF_WINIT, b_init,
                               nullptr, out + OUT_Z_OFF, nullptr, nullptr);

    // ---- SDE scan: 3 kernels/step ----
    for (int k = 0; k < NSTEP; k++) {
        const float* z = out + OUT_Z_OFF + (size_t)k * ZSLICE;
        float* zn = out + OUT_Z_OFF + (size_t)(k+1) * ZSLICE;
        dg1_k<<<dim3(BATCH/128, 4), blk, 65536>>>(z, wdgh, wdgl, bdg, w0dg, ts, k,
                                                  ah2, al2, gh2, gl2);
        d2_k<<<dim3(BATCH/128, 1), blk, 196608>>>(ah, al, wh+OFF_WD2, wl+OFF_WD2,
                                                  bd2, bh2, bl2);
        d3g2_k<<<dim3(BATCH/128, 1), blk, 98304>>>(bh, bl, gh, gl,
                                                   wh+OFF_WD3, wl+OFF_WD3,
                                                   wh+OFF_WG2, wl+OFF_WG2,
                                                   bd3, bg2, z, ts, k, noise, zn);
    }
}